// round 17
// baseline (speedup 1.0000x reference)
#include <cuda_runtime.h>
#include <cuda_bf16.h>
#include <cstdint>

#define TSTEPS 8192
#define NN     1024

// Scratch (device globals; no allocation allowed in kernel_launch)
__device__ float g_I[(size_t)TSTEPS * NN];   // dense fallback: I_all = X @ W1^T
__device__ float g_S[TSTEPS];                // per-step weighted spike sum
__device__ float g_P[(size_t)TSTEPS * 32];   // per-step per-warp partial sums
__device__ int   g_cnt[NN];                  // nonzeros per W1 row
__device__ __align__(16) int   g_col[NN];    // col of the single nonzero (if nnz<=1)
__device__ __align__(16) float g_val[NN];    // val of the single nonzero
__device__ int   g_maxnnz;                   // max row nnz; <=1 -> sparse fast path

// ---------------------------------------------------------------------------
// Packed fp32x2 helpers (Blackwell FFMA2)
// ---------------------------------------------------------------------------
__device__ __forceinline__ unsigned long long pack_dup(float x) {
    unsigned long long r;
    asm("mov.b64 %0, {%1, %1};" : "=l"(r) : "f"(x));
    return r;
}
__device__ __forceinline__ void ffma2(unsigned long long& d,
                                      unsigned long long a,
                                      unsigned long long b) {
    asm("fma.rn.f32x2 %0, %1, %2, %0;" : "+l"(d) : "l"(a), "l"(b));
}

// ---------------------------------------------------------------------------
// Kernel 0a: analyze W1 sparsity. One warp per row.
// ---------------------------------------------------------------------------
__global__ __launch_bounds__(256)
void analyze_kernel(const float* __restrict__ W1)
{
    const int warp = (blockIdx.x * blockDim.x + threadIdx.x) >> 5;
    const int lane = threadIdx.x & 31;
    if (warp >= NN) return;
    const float* row = W1 + (size_t)warp * NN;

    int   cnt = 0, col = 0;
    float val = 0.f;
#pragma unroll 4
    for (int c = lane; c < NN; c += 32) {
        float w = row[c];
        if (w != 0.f) { cnt++; col = c; val = w; }
    }
    int total = cnt;
#pragma unroll
    for (int o = 16; o > 0; o >>= 1)
        total += __shfl_xor_sync(0xffffffffu, total, o);
    unsigned mask = __ballot_sync(0xffffffffu, cnt > 0);
    int src = (mask != 0u) ? (__ffs(mask) - 1) : 0;
    col = __shfl_sync(0xffffffffu, col, src);
    val = __shfl_sync(0xffffffffu, val, src);
    if (lane == 0) {
        g_cnt[warp] = total;
        g_col[warp] = (mask != 0u) ? col : 0;
        g_val[warp] = (mask != 0u) ? val : 0.f;
    }
}

// ---------------------------------------------------------------------------
// Kernel 0b: g_maxnnz = max(g_cnt)
// ---------------------------------------------------------------------------
__global__ __launch_bounds__(256)
void maxnnz_kernel()
{
    const int tid = threadIdx.x;
    int m = 0;
#pragma unroll
    for (int i = tid; i < NN; i += 256) m = max(m, g_cnt[i]);
#pragma unroll
    for (int o = 16; o > 0; o >>= 1)
        m = max(m, __shfl_xor_sync(0xffffffffu, m, o));
    __shared__ int ws[8];
    if ((tid & 31) == 0) ws[tid >> 5] = m;
    __syncthreads();
    if (tid < 8) {
        int x = ws[tid];
#pragma unroll
        for (int o = 4; o > 0; o >>= 1)
            x = max(x, __shfl_xor_sync(0xffu, x, o));
        if (tid == 0) g_maxnnz = x;
    }
}

// ---------------------------------------------------------------------------
// Kernel 1 (dense fallback): C = A * B^T. Early-exits when W1 is 1-sparse.
// ---------------------------------------------------------------------------
__global__ __launch_bounds__(256, 2)
void gemm_nt_kernel(const float* __restrict__ A, const float* __restrict__ B,
                    int M, int N, int K)
{
    if (g_maxnnz <= 1) return;   // sparse fast path active -> dead launch

    constexpr int TM = 128, TN = 128, TK = 16;
    __shared__ float As[2][TK][TM + 4];
    __shared__ float Bs[2][TK][TN + 4];

    const int tid = threadIdx.x;
    const int bm = blockIdx.y * TM;
    const int bn = blockIdx.x * TN;

    const int lr = tid >> 2;
    const int lk = (tid & 3) * 4;

    const float* Ag = A + (size_t)(bm + lr) * K + lk;
    const float* Bg = B + (size_t)(bn + lr) * K + lk;

    const int tm = (tid >> 4) * 8;
    const int tn = (tid & 15) * 8;

    unsigned long long acc[8][4];
#pragma unroll
    for (int i = 0; i < 8; i++)
#pragma unroll
        for (int j = 0; j < 4; j++) acc[i][j] = 0ull;

    {
        float4 a0 = *(const float4*)(Ag);
        float4 a1 = *(const float4*)(Ag + (size_t)64 * K);
        float4 b0 = *(const float4*)(Bg);
        float4 b1 = *(const float4*)(Bg + (size_t)64 * K);
        As[0][lk + 0][lr]      = a0.x; As[0][lk + 1][lr]      = a0.y;
        As[0][lk + 2][lr]      = a0.z; As[0][lk + 3][lr]      = a0.w;
        As[0][lk + 0][lr + 64] = a1.x; As[0][lk + 1][lr + 64] = a1.y;
        As[0][lk + 2][lr + 64] = a1.z; As[0][lk + 3][lr + 64] = a1.w;
        Bs[0][lk + 0][lr]      = b0.x; Bs[0][lk + 1][lr]      = b0.y;
        Bs[0][lk + 2][lr]      = b0.z; Bs[0][lk + 3][lr]      = b0.w;
        Bs[0][lk + 0][lr + 64] = b1.x; Bs[0][lk + 1][lr + 64] = b1.y;
        Bs[0][lk + 2][lr + 64] = b1.z; Bs[0][lk + 3][lr + 64] = b1.w;
    }
    __syncthreads();

    int buf = 0;
#pragma unroll 1
    for (int kt = TK; kt <= K; kt += TK) {
        const bool last = (kt == K);
        float4 na0, na1, nb0, nb1;
        if (!last) {
            na0 = *(const float4*)(Ag + kt);
            na1 = *(const float4*)(Ag + (size_t)64 * K + kt);
            nb0 = *(const float4*)(Bg + kt);
            nb1 = *(const float4*)(Bg + (size_t)64 * K + kt);
        }

#pragma unroll
        for (int k = 0; k < TK; k++) {
            float4 af0 = *(const float4*)&As[buf][k][tm];
            float4 af1 = *(const float4*)&As[buf][k][tm + 4];
            ulonglong2 bq0 = *(const ulonglong2*)&Bs[buf][k][tn];
            ulonglong2 bq1 = *(const ulonglong2*)&Bs[buf][k][tn + 4];
            unsigned long long br[4] = {bq0.x, bq0.y, bq1.x, bq1.y};
            float ar[8] = {af0.x, af0.y, af0.z, af0.w,
                           af1.x, af1.y, af1.z, af1.w};
#pragma unroll
            for (int i = 0; i < 8; i++) {
                const unsigned long long ad = pack_dup(ar[i]);
#pragma unroll
                for (int j = 0; j < 4; j++)
                    ffma2(acc[i][j], ad, br[j]);
            }
        }

        if (!last) {
            const int nb = buf ^ 1;
            As[nb][lk + 0][lr]      = na0.x; As[nb][lk + 1][lr]      = na0.y;
            As[nb][lk + 2][lr]      = na0.z; As[nb][lk + 3][lr]      = na0.w;
            As[nb][lk + 0][lr + 64] = na1.x; As[nb][lk + 1][lr + 64] = na1.y;
            As[nb][lk + 2][lr + 64] = na1.z; As[nb][lk + 3][lr + 64] = na1.w;
            Bs[nb][lk + 0][lr]      = nb0.x; Bs[nb][lk + 1][lr]      = nb0.y;
            Bs[nb][lk + 2][lr]      = nb0.z; Bs[nb][lk + 3][lr]      = nb0.w;
            Bs[nb][lk + 0][lr + 64] = nb1.x; Bs[nb][lk + 1][lr + 64] = nb1.y;
            Bs[nb][lk + 2][lr + 64] = nb1.z; Bs[nb][lk + 3][lr + 64] = nb1.w;
            __syncthreads();
            buf = nb;
        }
    }

#pragma unroll
    for (int i = 0; i < 8; i++) {
        float* Cr = g_I + (size_t)(bm + tm + i) * N + bn + tn;
        ulonglong2 w0; w0.x = acc[i][0]; w0.y = acc[i][1];
        ulonglong2 w1; w1.x = acc[i][2]; w1.y = acc[i][3];
        *(ulonglong2*)(Cr)     = w0;
        *(ulonglong2*)(Cr + 4) = w1;
    }
}

// ---------------------------------------------------------------------------
// Izhikevich Euler step — verbatim numerics of the R4/R11/R12/R13 passing
// kernels. FROZEN: any rounding-shape change flips spikes (R8/R10/R15).
// In must arrive as a pre-rounded value.
// ---------------------------------------------------------------------------
__device__ __forceinline__ void izh_step(float In, float dtn, float dta,
                                         float bn, float cn, float dn, float thn,
                                         float& v, float& u, float& s)
{
    const float poly = 0.04f * v * v + 5.0f * v + 140.0f - u + In;
    const float vn = v + dtn * poly;
    const float un = u + dta * (bn * v - u);
    const bool  f  = (vn > thn);
    s = f ? 1.0f : 0.0f;
    v = f ? cn : vn;
    u = fmaf(dn, s, un);   // un + d*s, exact for s in {0,1}
}

// ---------------------------------------------------------------------------
// Kernel 2: per-neuron serial scan (R13 structure, step body untouched).
// ONE neuron per thread, 32 one-warp blocks. PF=32 raw prefetch.
// New vs R13 (both changes leave step inputs bit-identical):
//  * gathers X directly on the sparse path; In = __fmul_rn(w, x) — explicit
//    intrinsic = contraction barrier, value bit-equal to the old expand+load
//    (rn(w*x)). Dense path reads g_I with w = 1.0f (rn(1*x) = x). -> no
//    expand kernel, 13.6us saved.
//  * fused per-warp rowsum partial: warp-reduce of w2[n]*s per step into
//    g_P[t*32 + block]. Scan is chain-bound (R12 vs R13), so the ~15 extra
//    issue cycles hide under the ~60cyc dependence chain. Only `decoded`
//    (1e-3 slack) sees the reordered summation.
// ---------------------------------------------------------------------------
__global__ __launch_bounds__(32)
void scan_kernel(const float* __restrict__ X,
                 const float* __restrict__ st0,
                 const float* __restrict__ a_, const float* __restrict__ b_,
                 const float* __restrict__ c_, const float* __restrict__ d_,
                 const float* __restrict__ th_, const float* __restrict__ dt_,
                 const float* __restrict__ w2,
                 float* __restrict__ spikes, float* __restrict__ states)
{
    const int lane = threadIdx.x;
    const int blk  = blockIdx.x;           // 0..31
    const int n    = blk * 32 + lane;      // 0..1023

    float v = st0[n];
    float u = st0[NN + n];
    const float an  = a_[n],  bn  = b_[n];
    const float cn  = c_[n],  dn  = d_[n];
    const float thn = th_[n], dtn = dt_[n];
    const float dta = dtn * an;
    const float w2n = w2[n];

    const bool  sparse = (g_maxnnz <= 1);
    const int   col    = sparse ? g_col[n] : 0;
    const float w      = sparse ? g_val[n] : 1.0f;
    const float* src   = sparse ? (X + col) : (g_I + n);   // stride NN

    float* sp = spikes + n;          // stride NN
    float* vp = states + n;          // stride 2*NN
    float* up = states + NN + n;
    float* pp = g_P + blk;           // stride 32

    constexpr int PF = 32;           // deep pipeline: 32 outstanding LDG.32
    float pf[PF];
    float s;

#pragma unroll
    for (int i = 0; i < PF; i++) pf[i] = src[(size_t)i * NN];

#pragma unroll 1
    for (int t0 = 0; t0 < TSTEPS - PF; t0 += PF) {   // 255 iterations
#pragma unroll
        for (int k = 0; k < PF; k++) {
            const int t = t0 + k;
            const float In = __fmul_rn(w, pf[k]);    // explicit rounding barrier
            pf[k] = src[(size_t)(t + PF) * NN];      // raw prefetch, no consumer

            izh_step(In, dtn, dta, bn, cn, dn, thn, v, u, s);

            sp[(size_t)t * NN]     = s;
            vp[(size_t)t * 2 * NN] = v;
            up[(size_t)t * 2 * NN] = u;

            // fused rowsum partial (off the carried chain; decode-only data)
            float psum = w2n * s;
#pragma unroll
            for (int o = 16; o > 0; o >>= 1)
                psum += __shfl_xor_sync(0xffffffffu, psum, o);
            if (lane == 0) pp[(size_t)t * 32] = psum;
        }
    }
#pragma unroll
    for (int k = 0; k < PF; k++) {
        const int t = TSTEPS - PF + k;
        const float In = __fmul_rn(w, pf[k]);
        izh_step(In, dtn, dta, bn, cn, dn, thn, v, u, s);
        sp[(size_t)t * NN]     = s;
        vp[(size_t)t * 2 * NN] = v;
        up[(size_t)t * 2 * NN] = u;
        float psum = w2n * s;
#pragma unroll
        for (int o = 16; o > 0; o >>= 1)
            psum += __shfl_xor_sync(0xffffffffu, psum, o);
        if (lane == 0) pp[(size_t)t * 32] = psum;
    }
}

// ---------------------------------------------------------------------------
// Kernel 3: fold 32 partials per timestep: g_S[t] = sum_b g_P[t*32+b].
// One thread per t; each thread reads a contiguous 128B row.
// ---------------------------------------------------------------------------
__global__ __launch_bounds__(256)
void rowsum2_kernel()
{
    const int t = blockIdx.x * 256 + threadIdx.x;   // 0..8191
    const float4* p = (const float4*)(g_P + (size_t)t * 32);
    float sum = 0.f;
#pragma unroll
    for (int i = 0; i < 8; i++) {
        const float4 q = p[i];
        sum += q.x; sum += q.y; sum += q.z; sum += q.w;
    }
    g_S[t] = sum;
}

// ---------------------------------------------------------------------------
// Kernel 4: parallel decode scan (affine composition, Hillis-Steele)
// ---------------------------------------------------------------------------
__global__ __launch_bounds__(1024)
void decode_scan_kernel(const float* __restrict__ leak,
                        float* __restrict__ decoded)
{
    constexpr int C = TSTEPS / 1024;   // 8
    __shared__ float s_scale[1024];
    __shared__ float s_off[1024];

    const int tid = threadIdx.x;
    const float L = leak[0];
    const int base = tid * C;

    float vals[C];
#pragma unroll
    for (int k = 0; k < C; k++) vals[k] = g_S[base + k];

    float dm = 0.f;
#pragma unroll
    for (int k = 0; k < C; k++) dm = L * dm + vals[k];
    float L2 = L * L, L4 = L2 * L2, L8 = L4 * L4;

    float myS = L8, myO = dm;
    s_scale[tid] = myS; s_off[tid] = myO;
    __syncthreads();

    for (int d = 1; d < 1024; d <<= 1) {
        float ps = 1.f, po = 0.f;
        if (tid >= d) { ps = s_scale[tid - d]; po = s_off[tid - d]; }
        __syncthreads();
        myO = myS * po + myO;
        myS = myS * ps;
        s_scale[tid] = myS; s_off[tid] = myO;
        __syncthreads();
    }

    const float carry_in = (tid == 0) ? 0.f : s_off[tid - 1];

    dm = carry_in;
#pragma unroll
    for (int k = 0; k < C; k++) {
        dm = L * dm + vals[k];
        decoded[base + k] = dm;
    }
}

// ---------------------------------------------------------------------------
extern "C" void kernel_launch(void* const* d_in, const int* in_sizes, int n_in,
                              void* d_out, int out_size)
{
    const float* X    = (const float*)d_in[0];   // [T, N]
    const float* st0  = (const float*)d_in[1];   // [2, N]
    const float* W1   = (const float*)d_in[2];   // [N, N]
    const float* W2   = (const float*)d_in[3];   // [1, N]
    const float* a    = (const float*)d_in[4];
    const float* b    = (const float*)d_in[5];
    const float* c    = (const float*)d_in[6];
    const float* d    = (const float*)d_in[7];
    const float* th   = (const float*)d_in[8];
    const float* dt   = (const float*)d_in[9];
    const float* leak = (const float*)d_in[10];

    float* out     = (float*)d_out;
    float* spikes  = out;                                       // [T, N]
    float* states  = out + (size_t)TSTEPS * NN;                 // [T, 2, N]
    float* decoded = out + (size_t)TSTEPS * NN * 3;             // [T, 1]

    // 0) W1 sparsity analysis
    analyze_kernel<<<NN / 8, 256>>>(W1);
    maxnnz_kernel<<<1, 256>>>();

    // 1) dense fallback GEMM only (dead launch when W1 is <=1-sparse);
    //    sparse path needs no materialization — the scan gathers X directly.
    dim3 ggrid(NN / 128, TSTEPS / 128);
    gemm_nt_kernel<<<ggrid, 256>>>(X, W1, TSTEPS, NN, NN);

    // 2) per-neuron scan: R13 step, X-gather via __fmul_rn, fused rowsum
    scan_kernel<<<32, 32>>>(X, st0, a, b, c, d, th, dt, W2, spikes, states);

    // 3) fold per-warp partials into g_S
    rowsum2_kernel<<<TSTEPS / 256, 256>>>();

    // 4) decode leaky integrator (parallel affine scan)
    decode_scan_kernel<<<1, 1024>>>(leak, decoded);
}